// round 13
// baseline (speedup 1.0000x reference)
#include <cuda_runtime.h>

#define HH   256
#define P5   1024
#define NQ   128
#define GRID_MAIN  152   // GB300 SM count
#define BLOCK_MAIN 384   // 12 warps/SM, 3/SMSP; 2 points x 2 h per thread

__device__ float g_w2r[HH];
__device__ float g_c;

__device__ __forceinline__ float warp_sum(float v) {
    #pragma unroll
    for (int o = 16; o; o >>= 1) v += __shfl_xor_sync(0xffffffffu, v, o);
    return v;
}

// Pack z0,z1 -> f16x2 and tanh both in ONE MUFU op; result stays as raw b32.
__device__ __forceinline__ unsigned tanh2_raw(float z0, float z1) {
    unsigned t;
    asm("{\n\t"
        ".reg .b32 p;\n\t"
        "cvt.rn.f16x2.f32 p, %2, %1;\n\t"   // p.lo = z0, p.hi = z1
        "tanh.approx.f16x2 %0, p;\n\t"
        "}"
        : "=r"(t) : "f"(z0), "f"(z1));
    return t;
}

// ---------------------------------------------------------------------------
// Kernel 1 (fused setup + w2r): 128 blocks x 256 threads. (unchanged, proven)
// ---------------------------------------------------------------------------
__global__ __launch_bounds__(256)
void w2r_fused_kernel(
    const float* __restrict__ eq,
    const float* __restrict__ q0, const float* __restrict__ q1,
    const float* __restrict__ q2, const float* __restrict__ q3,
    const float* __restrict__ q4,
    const float* __restrict__ Wq0, const float* __restrict__ bq0,
    const float* __restrict__ Wq1, const float* __restrict__ bq1,
    const float* __restrict__ Wq2, const float* __restrict__ bq2,
    const float* __restrict__ Wq3, const float* __restrict__ bq3,
    const float* __restrict__ Wq4, const float* __restrict__ bq4,
    const float* __restrict__ bx2,
    const float* __restrict__ Wx2)
{
    __shared__ float s[5][64];
    __shared__ float t01[16][16];
    __shared__ float t23[16][16];
    __shared__ float partA[5][4], partB[5][4];
    __shared__ float sA[5], sB[5];
    __shared__ float red[8];

    const int tid  = threadIdx.x;
    const int lane = tid & 31;
    const int wrp  = tid >> 5;
    const int h0   = blockIdx.x * 2;

    const float4 wrow0 = reinterpret_cast<const float4*>(Wx2 + h0 * P5)[tid];
    const float4 wrow1 = reinterpret_cast<const float4*>(Wx2 + (h0 + 1) * P5)[tid];

    const float eqv = eq[0];

    if (tid < NQ) {
        const float* qp[5] = {q0, q1, q2, q3, q4};
        #pragma unroll
        for (int i = 0; i < 5; i++) {
            float q = qp[i][tid];
            float y = __expf(-q * q * eqv);
            float a = warp_sum(y * q);
            float b = warp_sum(y);
            if (lane == 0) { partA[i][wrp] = a; partB[i][wrp] = b; }
        }
    }
    __syncthreads();
    if (tid < 5) {
        sA[tid] = partA[tid][0] + partA[tid][1] + partA[tid][2] + partA[tid][3];
        sB[tid] = partB[tid][0] + partB[tid][1] + partB[tid][2] + partB[tid][3];
    }
    __syncthreads();

    if (tid < 64) {
        s[0][tid] = sA[0] * Wq0[tid] + sB[0] * bq0[tid];
        s[1][tid] = sA[1] * Wq1[tid] + sB[1] * bq1[tid];
        s[2][tid] = sA[2] * Wq2[tid] + sB[2] * bq2[tid];
        s[3][tid] = sA[3] * Wq3[tid] + sB[3] * bq3[tid];
        s[4][tid] = sA[4] * Wq4[tid] + sB[4] * bq4[tid];
    }
    __syncthreads();

    {
        int pq = tid >> 4;
        int x  = tid & 15;
        t01[x][pq] = s[0][(pq >> 2) * 16 + x] * s[1][(pq & 3) * 16 + x];
        t23[x][pq] = s[2][(pq >> 2) * 16 + x] * s[3][(pq & 3) * 16 + x];
    }
    __syncthreads();

    const int bd = tid >> 4;
    const int fm = tid & 15;
    float a0 = 0.f, a1 = 0.f, a2 = 0.f, a3 = 0.f;
    #pragma unroll
    for (int x = 0; x < 16; x++) {
        float u = t01[x][bd] * t23[x][fm];
        a0 = fmaf(u, s[4][x],      a0);
        a1 = fmaf(u, s[4][16 + x], a1);
        a2 = fmaf(u, s[4][32 + x], a2);
        a3 = fmaf(u, s[4][48 + x], a3);
    }

    float d0 = wrow0.x * a0 + wrow0.y * a1 + wrow0.z * a2 + wrow0.w * a3;
    float d1 = wrow1.x * a0 + wrow1.y * a1 + wrow1.z * a2 + wrow1.w * a3;
    d0 = warp_sum(d0);
    d1 = warp_sum(d1);
    if (lane == 0) red[wrp] = d0;
    __syncthreads();
    if (tid == 0) {
        float t = 0.f;
        #pragma unroll
        for (int w = 0; w < 8; w++) t += red[w];
        g_w2r[h0] = t;
    }
    __syncthreads();
    if (lane == 0) red[wrp] = d1;
    __syncthreads();
    if (tid == 0) {
        float t = 0.f;
        #pragma unroll
        for (int w = 0; w < 8; w++) t += red[w];
        g_w2r[h0 + 1] = t;
    }

    if (blockIdx.x == 0) {
        float4 bv = reinterpret_cast<const float4*>(bx2)[tid];
        float cp = a0 * bv.x + a1 * bv.y + a2 * bv.z + a3 * bv.w;
        cp = warp_sum(cp);
        __syncthreads();
        if (lane == 0) red[wrp] = cp;
        __syncthreads();
        if (tid == 0) {
            float c = 0.f;
            #pragma unroll
            for (int w = 0; w < 8; w++) c += red[w];
            g_c = c;
        }
    }
}

// ---------------------------------------------------------------------------
// Kernel 2: out[n] = c + sum_h tanh(z_h(n)) * w2r[h].
// Tile: 2 points x 2 h per thread. One MUFU.TANH.F16X2 per (point, h-pair);
// f16 results unpacked by exact integer bit surgery (ALU pipe):
//   as_float(sign | mag<<13) == tanh * 2^-112  (exact incl. subnormals).
// Accumulate in the 2^-112-scaled domain; epilogue FMA applies 2^112 + c.
// LDS (wa/wb/rp) amortized over both points -> ~9 insts per tanh-eval.
// ---------------------------------------------------------------------------
__global__ __launch_bounds__(BLOCK_MAIN)
void main_kernel(const float* __restrict__ input,
                 const float* __restrict__ Wx1,
                 const float* __restrict__ bx1,
                 float* __restrict__ out, int N)
{
    __shared__ float4 sW[HH];        // {wx, wy, wz, b} per h
    __shared__ float2 sRp[HH / 2];   // {w2r[2j], w2r[2j+1]}
    __shared__ float  sC;
    const int tid = threadIdx.x;
    if (tid < HH) {
        sW[tid] = make_float4(Wx1[tid], Wx1[HH + tid], Wx1[2 * HH + tid], bx1[tid]);
        if (tid < HH / 2)
            sRp[tid] = make_float2(g_w2r[2 * tid], g_w2r[2 * tid + 1]);
        if (tid == 0) sC = g_c;
    }
    __syncthreads();

    const int ppb  = (N + GRID_MAIN - 1) / GRID_MAIN;   // 658 for N=100000
    const int base = blockIdx.x * ppb;
    const int end  = min(base + ppb, N);
    const float c  = sC;

    for (int c0 = base; c0 < end; c0 += 2 * BLOCK_MAIN) {
        const int  n0 = c0 + tid;
        const int  n1 = n0 + BLOCK_MAIN;
        const bool v0 = n0 < end;
        const bool v1 = n1 < end;

        float x00 = 0.f, x01 = 0.f, x02 = 0.f;
        float x10 = 0.f, x11 = 0.f, x12 = 0.f;
        if (v0) { x00 = input[3*n0]; x01 = input[3*n0+1]; x02 = input[3*n0+2]; }
        if (v1) { x10 = input[3*n1]; x11 = input[3*n1+1]; x12 = input[3*n1+2]; }

        float acc0 = 0.f, acc1 = 0.f;    // scaled domain (x 2^-112)
        #pragma unroll 4
        for (int hp = 0; hp < HH / 2; hp++) {
            float4 wa = sW[2 * hp];
            float4 wb = sW[2 * hp + 1];
            float2 rp = sRp[hp];

            // point 0, both h
            float z0a = fmaf(x02, wa.z, fmaf(x01, wa.y, fmaf(x00, wa.x, wa.w)));
            float z0b = fmaf(x02, wb.z, fmaf(x01, wb.y, fmaf(x00, wb.x, wb.w)));
            // point 1, both h
            float z1a = fmaf(x12, wa.z, fmaf(x11, wa.y, fmaf(x10, wa.x, wa.w)));
            float z1b = fmaf(x12, wb.z, fmaf(x11, wb.y, fmaf(x10, wb.x, wb.w)));

            unsigned t0 = tanh2_raw(z0a, z0b);
            unsigned t1 = tanh2_raw(z1a, z1b);

            unsigned lo0 = ((t0 << 16) & 0x80000000u) | ((t0 & 0x7FFFu) << 13);
            unsigned hi0 = (t0 & 0x80000000u) | ((t0 >> 3) & 0x0FFFE000u);
            unsigned lo1 = ((t1 << 16) & 0x80000000u) | ((t1 & 0x7FFFu) << 13);
            unsigned hi1 = (t1 & 0x80000000u) | ((t1 >> 3) & 0x0FFFE000u);

            acc0 = fmaf(__uint_as_float(lo0), rp.x, acc0);
            acc0 = fmaf(__uint_as_float(hi0), rp.y, acc0);
            acc1 = fmaf(__uint_as_float(lo1), rp.x, acc1);
            acc1 = fmaf(__uint_as_float(hi1), rp.y, acc1);
        }
        if (v0) out[n0] = fmaf(acc0, 0x1p+112f, c);
        if (v1) out[n1] = fmaf(acc1, 0x1p+112f, c);
    }
}

// ---------------------------------------------------------------------------
extern "C" void kernel_launch(void* const* d_in, const int* in_sizes, int n_in,
                              void* d_out, int out_size)
{
    const float* input = (const float*)d_in[0];
    const float* eq    = (const float*)d_in[1];
    const float* q0    = (const float*)d_in[2];
    const float* q1    = (const float*)d_in[3];
    const float* q2    = (const float*)d_in[4];
    const float* q3    = (const float*)d_in[5];
    const float* q4    = (const float*)d_in[6];
    const float* Wx1   = (const float*)d_in[7];
    const float* bx1   = (const float*)d_in[8];
    const float* Wx2   = (const float*)d_in[9];
    const float* bx2   = (const float*)d_in[10];
    const float* Wq0   = (const float*)d_in[11];
    const float* bq0   = (const float*)d_in[12];
    const float* Wq1   = (const float*)d_in[13];
    const float* bq1   = (const float*)d_in[14];
    const float* Wq2   = (const float*)d_in[15];
    const float* bq2   = (const float*)d_in[16];
    const float* Wq3   = (const float*)d_in[17];
    const float* bq3   = (const float*)d_in[18];
    const float* Wq4   = (const float*)d_in[19];
    const float* bq4   = (const float*)d_in[20];

    const int N = in_sizes[0] / 3;

    w2r_fused_kernel<<<HH / 2, 256>>>(eq, q0, q1, q2, q3, q4,
                                      Wq0, bq0, Wq1, bq1, Wq2, bq2,
                                      Wq3, bq3, Wq4, bq4, bx2, Wx2);
    main_kernel<<<GRID_MAIN, BLOCK_MAIN>>>(input, Wx1, bx1, (float*)d_out, N);
}

// round 15
// speedup vs baseline: 1.2448x; 1.2448x over previous
#include <cuda_runtime.h>
#include <cuda_fp16.h>

#define HH   256
#define P5   1024
#define NQ   128
#define GRID_MAIN  152   // GB300 SM count
#define BLOCK_MAIN 768   // 24 warps/SM = 6/SMSP (proven necessary); 1 pt/thread

__device__ float g_w2r[HH];
__device__ float g_c;

__device__ __forceinline__ float warp_sum(float v) {
    #pragma unroll
    for (int o = 16; o; o >>= 1) v += __shfl_xor_sync(0xffffffffu, v, o);
    return v;
}

// bit-cast helpers (no SASS cost)
__device__ __forceinline__ unsigned h2_to_u(__half2 h) {
    return *reinterpret_cast<unsigned*>(&h);
}
__device__ __forceinline__ __half2 u_to_h2(unsigned u) {
    return *reinterpret_cast<__half2*>(&u);
}

// tanh.approx.f16x2 on an already-packed half2 (as raw b32). ONE XU op.
__device__ __forceinline__ unsigned tanh2_h2(unsigned z2) {
    unsigned t;
    asm("tanh.approx.f16x2 %0, %1;" : "=r"(t) : "r"(z2));
    return t;
}

// ---------------------------------------------------------------------------
// Kernel 1 (fused setup + w2r): 128 blocks x 256 threads. (unchanged, proven)
// ---------------------------------------------------------------------------
__global__ __launch_bounds__(256)
void w2r_fused_kernel(
    const float* __restrict__ eq,
    const float* __restrict__ q0, const float* __restrict__ q1,
    const float* __restrict__ q2, const float* __restrict__ q3,
    const float* __restrict__ q4,
    const float* __restrict__ Wq0, const float* __restrict__ bq0,
    const float* __restrict__ Wq1, const float* __restrict__ bq1,
    const float* __restrict__ Wq2, const float* __restrict__ bq2,
    const float* __restrict__ Wq3, const float* __restrict__ bq3,
    const float* __restrict__ Wq4, const float* __restrict__ bq4,
    const float* __restrict__ bx2,
    const float* __restrict__ Wx2)
{
    __shared__ float s[5][64];
    __shared__ float t01[16][16];
    __shared__ float t23[16][16];
    __shared__ float partA[5][4], partB[5][4];
    __shared__ float sA[5], sB[5];
    __shared__ float red[8];

    const int tid  = threadIdx.x;
    const int lane = tid & 31;
    const int wrp  = tid >> 5;
    const int h0   = blockIdx.x * 2;

    const float4 wrow0 = reinterpret_cast<const float4*>(Wx2 + h0 * P5)[tid];
    const float4 wrow1 = reinterpret_cast<const float4*>(Wx2 + (h0 + 1) * P5)[tid];

    const float eqv = eq[0];

    if (tid < NQ) {
        const float* qp[5] = {q0, q1, q2, q3, q4};
        #pragma unroll
        for (int i = 0; i < 5; i++) {
            float q = qp[i][tid];
            float y = __expf(-q * q * eqv);
            float a = warp_sum(y * q);
            float b = warp_sum(y);
            if (lane == 0) { partA[i][wrp] = a; partB[i][wrp] = b; }
        }
    }
    __syncthreads();
    if (tid < 5) {
        sA[tid] = partA[tid][0] + partA[tid][1] + partA[tid][2] + partA[tid][3];
        sB[tid] = partB[tid][0] + partB[tid][1] + partB[tid][2] + partB[tid][3];
    }
    __syncthreads();

    if (tid < 64) {
        s[0][tid] = sA[0] * Wq0[tid] + sB[0] * bq0[tid];
        s[1][tid] = sA[1] * Wq1[tid] + sB[1] * bq1[tid];
        s[2][tid] = sA[2] * Wq2[tid] + sB[2] * bq2[tid];
        s[3][tid] = sA[3] * Wq3[tid] + sB[3] * bq3[tid];
        s[4][tid] = sA[4] * Wq4[tid] + sB[4] * bq4[tid];
    }
    __syncthreads();

    {
        int pq = tid >> 4;
        int x  = tid & 15;
        t01[x][pq] = s[0][(pq >> 2) * 16 + x] * s[1][(pq & 3) * 16 + x];
        t23[x][pq] = s[2][(pq >> 2) * 16 + x] * s[3][(pq & 3) * 16 + x];
    }
    __syncthreads();

    const int bd = tid >> 4;
    const int fm = tid & 15;
    float a0 = 0.f, a1 = 0.f, a2 = 0.f, a3 = 0.f;
    #pragma unroll
    for (int x = 0; x < 16; x++) {
        float u = t01[x][bd] * t23[x][fm];
        a0 = fmaf(u, s[4][x],      a0);
        a1 = fmaf(u, s[4][16 + x], a1);
        a2 = fmaf(u, s[4][32 + x], a2);
        a3 = fmaf(u, s[4][48 + x], a3);
    }

    float d0 = wrow0.x * a0 + wrow0.y * a1 + wrow0.z * a2 + wrow0.w * a3;
    float d1 = wrow1.x * a0 + wrow1.y * a1 + wrow1.z * a2 + wrow1.w * a3;
    d0 = warp_sum(d0);
    d1 = warp_sum(d1);
    if (lane == 0) red[wrp] = d0;
    __syncthreads();
    if (tid == 0) {
        float t = 0.f;
        #pragma unroll
        for (int w = 0; w < 8; w++) t += red[w];
        g_w2r[h0] = t;
    }
    __syncthreads();
    if (lane == 0) red[wrp] = d1;
    __syncthreads();
    if (tid == 0) {
        float t = 0.f;
        #pragma unroll
        for (int w = 0; w < 8; w++) t += red[w];
        g_w2r[h0 + 1] = t;
    }

    if (blockIdx.x == 0) {
        float4 bv = reinterpret_cast<const float4*>(bx2)[tid];
        float cp = a0 * bv.x + a1 * bv.y + a2 * bv.z + a3 * bv.w;
        cp = warp_sum(cp);
        __syncthreads();
        if (lane == 0) red[wrp] = cp;
        __syncthreads();
        if (tid == 0) {
            float c = 0.f;
            #pragma unroll
            for (int w = 0; w < 8; w++) c += red[w];
            g_c = c;
        }
    }
}

// ---------------------------------------------------------------------------
// Kernel 2: out[n] = c + sum_h tanh(z_h(n)) * w2r[h].
// h in PAIRS, f16x2 end-to-end for z: weights pre-packed {w[2j], w[2j+1]}
// as half2 in smem; x broadcast to half2 once per point; z2 = 3 HFMA2;
// tanh.approx.f16x2 consumes z2 DIRECTLY (no pack cvt -> 1 XU op per 2 h).
// f16 results unpacked with exact integer bit surgery (ALU):
//   as_float(sign | mag<<13) == tanh * 2^-112  (exact incl. subnormals),
// accumulated in f32 (scaled domain), one epilogue FMA applies 2^112 + c.
// ---------------------------------------------------------------------------
__global__ __launch_bounds__(BLOCK_MAIN)
void main_kernel(const float* __restrict__ input,
                 const float* __restrict__ Wx1,
                 const float* __restrict__ bx1,
                 float* __restrict__ out, int N)
{
    __shared__ uint4  sWp[HH / 2];   // {wx2, wy2, wz2, b2} half2-packed per h-pair
    __shared__ float2 sRp[HH / 2];   // {w2r[2j], w2r[2j+1]}
    __shared__ float  sC;
    const int tid = threadIdx.x;
    if (tid < HH / 2) {
        const int j = 2 * tid;
        __half2 wx2 = __floats2half2_rn(Wx1[j],          Wx1[j + 1]);           // lo=2j
        __half2 wy2 = __floats2half2_rn(Wx1[HH + j],     Wx1[HH + j + 1]);
        __half2 wz2 = __floats2half2_rn(Wx1[2 * HH + j], Wx1[2 * HH + j + 1]);
        __half2 b2  = __floats2half2_rn(bx1[j],          bx1[j + 1]);
        uint4 w;
        w.x = h2_to_u(wx2); w.y = h2_to_u(wy2);
        w.z = h2_to_u(wz2); w.w = h2_to_u(b2);
        sWp[tid] = w;
        sRp[tid] = make_float2(g_w2r[j], g_w2r[j + 1]);
    }
    if (tid == 0) sC = g_c;
    __syncthreads();

    const int ppb  = (N + GRID_MAIN - 1) / GRID_MAIN;   // 658 for N=100000
    const int base = blockIdx.x * ppb;
    const int end  = min(base + ppb, N);
    const float c  = sC;

    for (int n0 = base; n0 < end; n0 += BLOCK_MAIN) {
        const int  n = n0 + tid;
        const bool v = n < end;
        float x0 = 0.f, x1 = 0.f, x2 = 0.f;
        if (v) { x0 = input[3 * n]; x1 = input[3 * n + 1]; x2 = input[3 * n + 2]; }

        const __half2 x0d = __float2half2_rn(x0);   // {x0, x0}
        const __half2 x1d = __float2half2_rn(x1);
        const __half2 x2d = __float2half2_rn(x2);

        float acc = 0.f;                 // scaled domain (x 2^-112)
        #pragma unroll 8
        for (int hp = 0; hp < HH / 2; hp++) {
            uint4  w  = sWp[hp];
            float2 rp = sRp[hp];

            __half2 z2 = __hfma2(x0d, u_to_h2(w.x),
                         __hfma2(x1d, u_to_h2(w.y),
                         __hfma2(x2d, u_to_h2(w.z),
                                 u_to_h2(w.w))));           // 3 HFMA2

            unsigned t = tanh2_h2(h2_to_u(z2));             // 1 XU op

            // exact f16 -> (tanh * 2^-112) as f32, pure ALU
            unsigned lo = ((t << 16) & 0x80000000u) | ((t & 0x7FFFu) << 13);
            unsigned hi = (t & 0x80000000u) | ((t >> 3) & 0x0FFFE000u);

            acc = fmaf(__uint_as_float(lo), rp.x, acc);
            acc = fmaf(__uint_as_float(hi), rp.y, acc);
        }
        if (v) out[n] = fmaf(acc, 0x1p+112f, c);
    }
}

// ---------------------------------------------------------------------------
extern "C" void kernel_launch(void* const* d_in, const int* in_sizes, int n_in,
                              void* d_out, int out_size)
{
    const float* input = (const float*)d_in[0];
    const float* eq    = (const float*)d_in[1];
    const float* q0    = (const float*)d_in[2];
    const float* q1    = (const float*)d_in[3];
    const float* q2    = (const float*)d_in[4];
    const float* q3    = (const float*)d_in[5];
    const float* q4    = (const float*)d_in[6];
    const float* Wx1   = (const float*)d_in[7];
    const float* bx1   = (const float*)d_in[8];
    const float* Wx2   = (const float*)d_in[9];
    const float* bx2   = (const float*)d_in[10];
    const float* Wq0   = (const float*)d_in[11];
    const float* bq0   = (const float*)d_in[12];
    const float* Wq1   = (const float*)d_in[13];
    const float* bq1   = (const float*)d_in[14];
    const float* Wq2   = (const float*)d_in[15];
    const float* bq2   = (const float*)d_in[16];
    const float* Wq3   = (const float*)d_in[17];
    const float* bq3   = (const float*)d_in[18];
    const float* Wq4   = (const float*)d_in[19];
    const float* bq4   = (const float*)d_in[20];

    const int N = in_sizes[0] / 3;

    w2r_fused_kernel<<<HH / 2, 256>>>(eq, q0, q1, q2, q3, q4,
                                      Wq0, bq0, Wq1, bq1, Wq2, bq2,
                                      Wq3, bq3, Wq4, bq4, bx2, Wx2);
    main_kernel<<<GRID_MAIN, BLOCK_MAIN>>>(input, Wx1, bx1, (float*)d_out, N);
}